// round 17
// baseline (speedup 1.0000x reference)
#include <cuda_runtime.h>
#include <math.h>

#define BB   4
#define SS   64
#define DDIM 512
#define HH   8
#define DH   64
#define DFF  2048
#define LLAY 2
#define VV   32128
#define TT   16
#define NEGV (-1e9f)

#define GF_RES  1
#define GF_RELU 2

#define NB 148
#define NT 512

// ---------------- scratch (device globals; no allocations) ----------------
__device__ float g_x  [BB*SS*DDIM];
__device__ float g_h  [BB*SS*DDIM];
__device__ float g_q  [BB*SS*DDIM];
__device__ float g_k  [BB*SS*DDIM];
__device__ float g_v  [BB*SS*DDIM];
__device__ float g_at [BB*SS*DDIM];
__device__ float g_ff [BB*SS*DFF];
__device__ float g_hs [BB*SS*DDIM];
__device__ float g_ckc[LLAY*BB*SS*DDIM];
__device__ float g_cvc[LLAY*BB*SS*DDIM];
__device__ float g_skc[LLAY*BB*TT*DDIM];
__device__ float g_svc[LLAY*BB*TT*DDIM];
__device__ float g_xd [BB*DDIM];
__device__ float g_qd [BB*DDIM];
__device__ float g_fd [BB*DFF];
__device__ float g_logits[BB*VV];
__device__ float g_part[3145728];
// per-head partial buffers: [h(8)][m(4)][512]
__device__ float g_p3[32*DDIM];
__device__ float g_p6[32*DDIM];
// FFN k-split partials: [kb(4)][m(4)][512]
__device__ float g_p8[16*DDIM];
// staged residual snapshots
__device__ float g_x2[BB*DDIM];   // x + self-proj (written in S3 by h==0)
__device__ float g_x3[BB*DDIM];   // x + self-proj + cross-proj (written in S4 by bid==0)
// distributed softmax stats: per (batch, block)
__device__ float g_stm[BB*NB];
__device__ float g_sts[BB*NB];
__device__ int   g_sti[BB*NB];
// flag barrier state (monotonic; replay-safe)
__device__ unsigned g_flag[NB];
__device__ unsigned g_rel;
__device__ unsigned g_zflag;

// ======================= encoder kernels =======================
__global__ void embed_kernel(const int* __restrict__ ids, const float* __restrict__ emb) {
    int row = blockIdx.x;
    int id  = ids[row];
    for (int d = threadIdx.x; d < DDIM; d += 256)
        g_x[row*DDIM + d] = emb[(size_t)id*DDIM + d];
}

__global__ void rmsnorm_kernel(const float* __restrict__ x, const float* __restrict__ w,
                               float* __restrict__ o) {
    int r = blockIdx.x, tid = threadIdx.x;
    __shared__ float red[256];
    float a = x[r*DDIM + tid];
    float b = x[r*DDIM + 256 + tid];
    red[tid] = a*a + b*b;
    __syncthreads();
    for (int s = 128; s > 0; s >>= 1) { if (tid < s) red[tid] += red[tid+s]; __syncthreads(); }
    float inv = rsqrtf(red[0] / (float)DDIM + 1e-6f);
    o[r*DDIM + tid]       = a * inv * w[tid];
    o[r*DDIM + 256 + tid] = b * inv * w[256 + tid];
}

__device__ __forceinline__ void gemm_split_body(const float* __restrict__ A,
                                                const float* __restrict__ W,
                                                float* __restrict__ pc,
                                                int M, int N, int K, int kbeg, int kend) {
    __shared__ float As[16][64];
    __shared__ float Bs[16][64];
    int row0 = blockIdx.y * 64, col0 = blockIdx.x * 64;
    int tid = threadIdx.x;
    int ty = tid / 16, tx = tid % 16;
    float acc[4][4];
    #pragma unroll
    for (int i = 0; i < 4; i++)
        #pragma unroll
        for (int j = 0; j < 4; j++) acc[i][j] = 0.f;

    for (int k0 = kbeg; k0 < kend; k0 += 16) {
        #pragma unroll
        for (int p = 0; p < 4; p++) {
            int i = tid + p*256;
            int r = i >> 4, c = i & 15;
            As[c][r] = A[(row0 + r)*K + k0 + c];
        }
        #pragma unroll
        for (int p = 0; p < 4; p++) {
            int i = tid + p*256;
            int r = i >> 6, c = i & 63;
            Bs[r][c] = W[(size_t)(k0 + r)*N + col0 + c];
        }
        __syncthreads();
        #pragma unroll
        for (int k = 0; k < 16; k++) {
            float a[4], b[4];
            #pragma unroll
            for (int i = 0; i < 4; i++) a[i] = As[k][ty*4 + i];
            #pragma unroll
            for (int j = 0; j < 4; j++) b[j] = Bs[k][tx*4 + j];
            #pragma unroll
            for (int i = 0; i < 4; i++)
                #pragma unroll
                for (int j = 0; j < 4; j++) acc[i][j] += a[i]*b[j];
        }
        __syncthreads();
    }
    #pragma unroll
    for (int i = 0; i < 4; i++) {
        int r = row0 + ty*4 + i;
        #pragma unroll
        for (int j = 0; j < 4; j++)
            pc[(size_t)r*N + col0 + tx*4 + j] = acc[i][j];
    }
}

__global__ void gemm_split(const float* __restrict__ A, const float* __restrict__ W,
                           float* __restrict__ part, int M, int N, int K, int KS) {
    int ksid = blockIdx.z;
    int kc = K / KS;
    gemm_split_body(A, W, part + (size_t)ksid*M*N, M, N, K, ksid*kc, ksid*kc + kc);
}

__global__ void gemm_split3(const float* __restrict__ A, const float* __restrict__ w0,
                            const float* __restrict__ w1, const float* __restrict__ w2,
                            float* __restrict__ part, int M, int N, int K, int KS) {
    int wsel = blockIdx.z / KS, ksid = blockIdx.z % KS;
    const float* W = (wsel == 0) ? w0 : (wsel == 1) ? w1 : w2;
    int kc = K / KS;
    gemm_split_body(A, W, part + ((size_t)wsel*KS + ksid)*M*N, M, N, K, ksid*kc, ksid*kc + kc);
}

__global__ void gemm_reduce(const float* __restrict__ part, const float* __restrict__ res,
                            float* __restrict__ C, int MN, int KS, int flags) {
    int i = (blockIdx.x*256 + threadIdx.x) * 4;
    if (i >= MN) return;
    float4 s = *(const float4*)(part + i);
    for (int k = 1; k < KS; k++) {
        float4 p = *(const float4*)(part + (size_t)k*MN + i);
        s.x += p.x; s.y += p.y; s.z += p.z; s.w += p.w;
    }
    if (flags & GF_RES) {
        float4 r = *(const float4*)(res + i);
        s.x += r.x; s.y += r.y; s.z += r.z; s.w += r.w;
    }
    if (flags & GF_RELU) {
        s.x = fmaxf(s.x, 0.f); s.y = fmaxf(s.y, 0.f);
        s.z = fmaxf(s.z, 0.f); s.w = fmaxf(s.w, 0.f);
    }
    *(float4*)(C + i) = s;
}

__global__ void gemm_reduce3(const float* __restrict__ part,
                             float* __restrict__ d0, float* __restrict__ d1,
                             float* __restrict__ d2, int MN, int KS) {
    int wsel = blockIdx.y;
    float* C = (wsel == 0) ? d0 : (wsel == 1) ? d1 : d2;
    const float* p = part + (size_t)wsel*KS*MN;
    int i = (blockIdx.x*256 + threadIdx.x) * 4;
    if (i >= MN) return;
    float4 s = *(const float4*)(p + i);
    for (int k = 1; k < KS; k++) {
        float4 q = *(const float4*)(p + (size_t)k*MN + i);
        s.x += q.x; s.y += q.y; s.z += q.z; s.w += q.w;
    }
    *(float4*)(C + i) = s;
}

__global__ void enc_attn(const float* __restrict__ Q, const float* __restrict__ K,
                         const float* __restrict__ V, const float* __restrict__ mask,
                         float* __restrict__ O) {
    int bh = blockIdx.x; int b = bh >> 3, h = bh & 7;
    int tid = threadIdx.x;
    __shared__ float Ks[64*65], Vs[64*65], sc[64], se[64];
    for (int i = tid; i < 4096; i += 64) {
        int r = i >> 6, c = i & 63;
        Ks[r*65 + c] = K[(size_t)(b*SS + r)*DDIM + h*DH + c];
        Vs[r*65 + c] = V[(size_t)(b*SS + r)*DDIM + h*DH + c];
    }
    __syncthreads();
    float bias = (1.f - mask[b*SS + tid]) * NEGV;
    for (int q = 0; q < SS; q++) {
        const float* qr = &Q[(size_t)(b*SS + q)*DDIM + h*DH];
        float s = 0.f;
        #pragma unroll 8
        for (int d = 0; d < DH; d++) s += qr[d]*Ks[tid*65 + d];
        sc[tid] = s * 0.125f + bias;
        __syncthreads();
        float mx = -1e30f;
        for (int j = 0; j < 64; j++) mx = fmaxf(mx, sc[j]);
        se[tid] = expf(sc[tid] - mx);
        __syncthreads();
        float den = 0.f;
        for (int j = 0; j < 64; j++) den += se[j];
        float o = 0.f;
        #pragma unroll 8
        for (int j = 0; j < 64; j++) o += se[j]*Vs[j*65 + tid];
        O[(size_t)(b*SS + q)*DDIM + h*DH + tid] = o / den;
        __syncthreads();
    }
}

// ======================= decode megakernel =======================
__shared__ float  s_xs[4*DFF];     // 32KB multipurpose
__shared__ float4 s_xt[DDIM];      // 8KB
__shared__ float  s_red[1104];
__shared__ float  s_sinv[4];
__shared__ float  s_wm[64];
__shared__ float  s_ws[64];
__shared__ int    s_wi[64];
__shared__ float  s_Mg[4];
__shared__ float  s_iSg[4];
__shared__ int    s_amg[4];

__device__ __forceinline__ void gridbar(unsigned& gen) {
    gen++;
    __syncthreads();
    if (blockIdx.x == 0) {
        if (threadIdx.x == 0) { __threadfence(); *(volatile unsigned*)&g_flag[0] = gen; }
        if (threadIdx.x < NB)
            while (*(volatile unsigned*)&g_flag[threadIdx.x] != gen) { }
        __syncthreads();
        if (threadIdx.x == 0) { __threadfence(); *(volatile unsigned*)&g_rel = gen; }
        __syncthreads();
    } else {
        if (threadIdx.x == 0) {
            __threadfence();
            *(volatile unsigned*)&g_flag[blockIdx.x] = gen;
            while (*(volatile unsigned*)&g_rel != gen) { }
            __threadfence();
        }
        __syncthreads();
    }
}

__device__ __forceinline__ void smerge(float& m, float& s, int& i,
                                       float m2, float s2, int i2) {
    float mm = fmaxf(m, m2);
    s = s*expf(m - mm) + s2*expf(m2 - mm);
    if (m2 > m || (m2 == m && i2 < i)) i = i2;
    m = mm;
}

// shared rms-stat helper: given per-thread v0..v3 (k=tid), compute s_sinv[0..3]
__device__ __forceinline__ void rms_stats(float v0, float v1, float v2, float v3) {
    int tid = threadIdx.x, lane = tid & 31, w = tid >> 5;
    float s0 = v0*v0, s1 = v1*v1, s2 = v2*v2, s3 = v3*v3;
    #pragma unroll
    for (int off = 16; off > 0; off >>= 1) {
        s0 += __shfl_xor_sync(0xffffffffu, s0, off);
        s1 += __shfl_xor_sync(0xffffffffu, s1, off);
        s2 += __shfl_xor_sync(0xffffffffu, s2, off);
        s3 += __shfl_xor_sync(0xffffffffu, s3, off);
    }
    if (lane == 0) {
        s_red[w] = s0; s_red[16 + w] = s1; s_red[32 + w] = s2; s_red[48 + w] = s3;
    }
    __syncthreads();
    if (tid < 4) {
        float s = 0.f;
        #pragma unroll
        for (int ww = 0; ww < 16; ww++) s += s_red[tid*16 + ww];
        s_sinv[tid] = rsqrtf(s / 512.0f + 1e-6f);
    }
    __syncthreads();
}

// K=512 prep (base x + optional 4-part P), ln optional, optional transpose
__device__ __forceinline__ void prep512p(const float* __restrict__ x,
                                         const float* __restrict__ P,
                                         const float* __restrict__ ln, bool xt) {
    int tid = threadIdx.x;
    float v0 = x[tid], v1 = x[512 + tid], v2 = x[1024 + tid], v3 = x[1536 + tid];
    if (P) {
        #pragma unroll
        for (int kb = 0; kb < 4; kb++) {
            v0 += P[(kb*4+0)*512 + tid];
            v1 += P[(kb*4+1)*512 + tid];
            v2 += P[(kb*4+2)*512 + tid];
            v3 += P[(kb*4+3)*512 + tid];
        }
    }
    if (ln) {
        float lw = ln[tid];
        rms_stats(v0, v1, v2, v3);
        v0 *= lw; v1 *= lw; v2 *= lw; v3 *= lw;
    }
    s_xs[tid] = v0; s_xs[512 + tid] = v1; s_xs[1024 + tid] = v2; s_xs[1536 + tid] = v3;
    if (xt) s_xt[tid] = make_float4(v0, v1, v2, v3);
    __syncthreads();
}

__device__ __forceinline__ void materialize_x(const float* __restrict__ P, int m) {
    int tid = threadIdx.x;
    float v = g_xd[m*512 + tid];
    #pragma unroll
    for (int kb = 0; kb < 4; kb++) v += P[(kb*4+m)*512 + tid];
    g_xd[m*512 + tid] = v;
}

__device__ __forceinline__ void prep_relu2048(const float* __restrict__ x) {
    const float4* xf = (const float4*)x;
    float4* sf = (float4*)s_xs;
    #pragma unroll
    for (int i = threadIdx.x; i < 2048; i += NT) {
        float4 p = xf[i];
        p.x = fmaxf(p.x, 0.f); p.y = fmaxf(p.y, 0.f);
        p.z = fmaxf(p.z, 0.f); p.w = fmaxf(p.w, 0.f);
        sf[i] = p;
    }
    __syncthreads();
}

template<int K>
__device__ __forceinline__ void gemv_tile(const float* __restrict__ W, int N, int tile,
                                          float* __restrict__ dst, int mstride,
                                          bool use_sinv) {
    constexpr int KC = K / 32;
    int tid = threadIdx.x;
    int w = tid >> 5, lane = tid & 31;
    int sub = lane >> 4, c = lane & 15;
    int ks = w*2 + sub;
    int col = tile*16 + c;
    const float* xp = s_xs + ks*KC;
    const float* wp = W + (size_t)(ks*KC)*N + col;
    float a0=0.f, a1=0.f, a2=0.f, a3=0.f;
    for (int k0 = 0; k0 < KC; k0 += 16) {
        #pragma unroll
        for (int k = 0; k < 16; k++) {
            float wv = wp[(size_t)(k0+k)*N];
            a0 += xp[k0+k]*wv; a1 += xp[K+k0+k]*wv;
            a2 += xp[2*K+k0+k]*wv; a3 += xp[3*K+k0+k]*wv;
        }
    }
    a0 += __shfl_xor_sync(0xffffffffu, a0, 16);
    a1 += __shfl_xor_sync(0xffffffffu, a1, 16);
    a2 += __shfl_xor_sync(0xffffffffu, a2, 16);
    a3 += __shfl_xor_sync(0xffffffffu, a3, 16);
    if (sub == 0) {
        s_red[(c*4+0)*17 + w] = a0;
        s_red[(c*4+1)*17 + w] = a1;
        s_red[(c*4+2)*17 + w] = a2;
        s_red[(c*4+3)*17 + w] = a3;
    }
    __syncthreads();
    if (tid < 64) {
        float s = 0.f;
        #pragma unroll
        for (int w2 = 0; w2 < 16; w2++) s += s_red[tid*17 + w2];
        int cc = tid >> 2, m = tid & 3;
        int oc = tile*16 + cc;
        if (use_sinv) s *= s_sinv[m];
        dst[(size_t)m*mstride + oc] = s;
    }
    __syncthreads();
}

template<int K, int KSB>
__device__ __forceinline__ void gemv_part(const float* __restrict__ W, int N, int tile, int kb,
                                          float* __restrict__ P, bool use_sinv) {
    constexpr int KB = K / KSB;
    constexpr int KC = KB / 32;
    int tid = threadIdx.x;
    int w = tid >> 5, lane = tid & 31;
    int sub = lane >> 4, c = lane & 15;
    int ks = w*2 + sub;
    int col = tile*16 + c;
    int row0 = kb*KB + ks*KC;
    const float* xp = s_xs + row0;
    const float* wp = W + (size_t)row0*N + col;
    float a0=0.f, a1=0.f, a2=0.f, a3=0.f;
    #pragma unroll
    for (int k = 0; k < KC; k++) {
        float wv = wp[(size_t)k*N];
        a0 += xp[k]*wv; a1 += xp[K+k]*wv; a2 += xp[2*K+k]*wv; a3 += xp[3*K+k]*wv;
    }
    a0 += __shfl_xor_sync(0xffffffffu, a0, 16);
    a1 += __shfl_xor_sync(0xffffffffu, a1, 16);
    a2 += __shfl_xor_sync(0xffffffffu, a2, 16);
    a3 += __shfl_xor_sync(0xffffffffu, a3, 16);
    if (sub == 0) {
        s_red[(c*4+0)*17 + w] = a0;
        s_red[(c*4+1)*17 + w] = a1;
        s_red[(c*4+2)*17 + w] = a2;
        s_red[(c*4+3)*17 + w] = a3;
    }
    __syncthreads();
    if (tid < 64) {
        float s = 0.f;
        #pragma unroll
        for (int w2 = 0; w2 < 16; w2++) s += s_red[tid*17 + w2];
        int cc = tid >> 2, m = tid & 3;
        int oc = tile*16 + cc;
        if (use_sinv) s *= s_sinv[m];
        P[(size_t)(kb*4+m)*N + oc] = s;
    }
    __syncthreads();
}

// warp-per-tile logits with fused per-block softmax stats
__device__ __forceinline__ void logits_warp_stats(const float* __restrict__ lm,
                                                  float* __restrict__ dst) {
    int tid = threadIdx.x;
    int lane = tid & 31, w = tid >> 5;
    int gw = blockIdx.x * (NT/32) + w;
    float si0 = s_sinv[0], si1 = s_sinv[1], si2 = s_sinv[2], si3 = s_sinv[3];
    int sub = lane >> 4, c = lane & 15;
    float stm0=-1e30f, stm1=-1e30f, stm2=-1e30f, stm3=-1e30f;
    float sts0=0.f, sts1=0.f, sts2=0.f, sts3=0.f;
    int   sti0=0, sti1=0, sti2=0, sti3=0;
    const int NTILE = VV / 16;
    for (int tile = gw; tile < NTILE; tile += NB*(NT/32)) {
        int col = tile*16 + c;
        const float4* xp = s_xt + sub*256;
        const float*  wp = lm + (size_t)(sub*256)*VV + col;
        float a0=0.f, a1=0.f, a2=0.f, a3=0.f;
        for (int k0 = 0; k0 < 256; k0 += 32) {
            float wv[32];
            #pragma unroll
            for (int k = 0; k < 32; k++) wv[k] = wp[(size_t)(k0+k)*VV];
            #pragma unroll
            for (int k = 0; k < 32; k++) {
                float4 x4 = xp[k0+k];
                a0 += x4.x*wv[k]; a1 += x4.y*wv[k]; a2 += x4.z*wv[k]; a3 += x4.w*wv[k];
            }
        }
        a0 += __shfl_xor_sync(0xffffffffu, a0, 16);
        a1 += __shfl_xor_sync(0xffffffffu, a1, 16);
        a2 += __shfl_xor_sync(0xffffffffu, a2, 16);
        a3 += __shfl_xor_sync(0xffffffffu, a3, 16);
        if (sub == 0) {
            float v0 = a0*si0, v1 = a1*si1, v2 = a2*si2, v3 = a3*si3;
            dst[(size_t)0*VV + col] = v0;
            dst[(size_t)1*VV + col] = v1;
            dst[(size_t)2*VV + col] = v2;
            dst[(size_t)3*VV + col] = v3;
            stm0 = v0; sts0 = 1.f; sti0 = col;
            stm1 = v1; sts1 = 1.f; sti1 = col;
            stm2 = v2; sts2 = 1.f; sti2 = col;
            stm3 = v3; sts3 = 1.f; sti3 = col;
        }
    }
    #pragma unroll
    for (int off = 16; off > 0; off >>= 1) {
        float m2, s2; int i2;
        m2 = __shfl_xor_sync(0xffffffffu, stm0, off); s2 = __shfl_xor_sync(0xffffffffu, sts0, off);
        i2 = __shfl_xor_sync(0xffffffffu, sti0, off); smerge(stm0, sts0, sti0, m2, s2, i2);
        m2 = __shfl_xor_sync(0xffffffffu, stm1, off); s2 = __shfl_xor_sync(0xffffffffu, sts1, off);
        i2 = __shfl_xor_sync(0xffffffffu, sti1, off); smerge(stm1, sts1, sti1, m2, s2, i2);
        m2 = __shfl_xor_sync(0xffffffffu, stm2, off); s2 = __shfl_xor_sync(0xffffffffu, sts2, off);
        i2 = __shfl_xor_sync(0xffffffffu, sti2, off); smerge(stm2, sts2, sti2, m2, s2, i2);
        m2 = __shfl_xor_sync(0xffffffffu, stm3, off); s2 = __shfl_xor_sync(0xffffffffu, sts3, off);
        i2 = __shfl_xor_sync(0xffffffffu, sti3, off); smerge(stm3, sts3, sti3, m2, s2, i2);
    }
    if (lane == 0) {
        s_wm[w*4+0] = stm0; s_ws[w*4+0] = sts0; s_wi[w*4+0] = sti0;
        s_wm[w*4+1] = stm1; s_ws[w*4+1] = sts1; s_wi[w*4+1] = sti1;
        s_wm[w*4+2] = stm2; s_ws[w*4+2] = sts2; s_wi[w*4+2] = sti2;
        s_wm[w*4+3] = stm3; s_ws[w*4+3] = sts3; s_wi[w*4+3] = sti3;
    }
    __syncthreads();
    if (tid < 4) {
        int b = tid;
        float m = s_wm[b], s = s_ws[b]; int i = s_wi[b];
        for (int ww = 1; ww < 16; ww++)
            smerge(m, s, i, s_wm[ww*4+b], s_ws[ww*4+b], s_wi[ww*4+b]);
        g_stm[b*NB + blockIdx.x] = m;
        g_sts[b*NB + blockIdx.x] = s;
        g_sti[b*NB + blockIdx.x] = i;
    }
    __syncthreads();
}

__global__ void __launch_bounds__(NT, 1)
decode_megakernel(const float* __restrict__ mask, const float* __restrict__ emb,
                  const float* __restrict__ sq, const float* __restrict__ sk,
                  const float* __restrict__ sv, const float* __restrict__ so,
                  const float* __restrict__ ln1, const float* __restrict__ cq,
                  const float* __restrict__ co, const float* __restrict__ ln2,
                  const float* __restrict__ w1, const float* __restrict__ w2,
                  const float* __restrict__ ln3, const float* __restrict__ lnf,
                  const float* __restrict__ lm, float* __restrict__ out) {
    const size_t DD2 = (size_t)DDIM*DDIM;
    const size_t DF  = (size_t)DDIM*DFF;
    int tid = threadIdx.x;
    int bid = blockIdx.x;

    unsigned gen = *(volatile unsigned*)&g_rel;

    if (bid < 4)
        g_xd[bid*DDIM + tid] = emb[tid];
    gridbar(gen);

    for (int t = 0; t < TT; t++) {
        for (int l = 0; l < LLAY; l++) {
            // ---- S1: rms(ln1) + QKV (96 blocks); l==1 folds FFN partials of layer 0 ----
            if (bid < 96) {
                prep512p(g_xd, (l == 1) ? g_p8 : nullptr, ln1 + l*DDIM, false);
                int seg = bid >> 5, ti = bid & 31;
                if (seg == 0) {
                    gemv_tile<DDIM>(sq + l*DD2, DDIM, ti, g_qd, DDIM, true);
                } else if (seg == 1) {
                    gemv_tile<DDIM>(sk + l*DD2, DDIM, ti,
                                    g_skc + (size_t)(l*BB*TT + t)*DDIM, TT*DDIM, true);
                } else {
                    gemv_tile<DDIM>(sv + l*DD2, DDIM, ti,
                                    g_svc + (size_t)(l*BB*TT + t)*DDIM, TT*DDIM, true);
                }
            }
            gridbar(gen);

            // ---- S2: per-head self-attn + O-proj partial (8 blocks, h=bid) ----
            if (bid < 8) {
                int h = bid;
                int nk = t + 1;
                float* S  = s_xs;          // scores [m*16+j]
                float* Pp = s_xs + 64;     // probs  [m*16+j]
                float* AO = s_xs + 128;    // attn_out [m*64+d]
                {
                    int m = tid >> 7, j = (tid >> 3) & 15, d8 = tid & 7;
                    float sc = 0.f;
                    if (j < nk) {
                        const float* qm = g_qd + m*DDIM + h*DH + d8*8;
                        const float* kr = g_skc + ((size_t)(l*BB+m)*TT + j)*DDIM + h*DH + d8*8;
                        #pragma unroll
                        for (int dd = 0; dd < 8; dd++) sc += qm[dd]*kr[dd];
                    }
                    sc += __shfl_xor_sync(0xffffffffu, sc, 1);
                    sc += __shfl_xor_sync(0xffffffffu, sc, 2);
                    sc += __shfl_xor_sync(0xffffffffu, sc, 4);
                    if (d8 == 0 && j < nk) S[m*16+j] = sc * 0.125f;
                }
                __syncthreads();
                if (tid < 4) {
                    float mx = -1e30f;
                    for (int jj = 0; jj < nk; jj++) mx = fmaxf(mx, S[tid*16+jj]);
                    float den = 0.f;
                    for (int jj = 0; jj < nk; jj++) {
                        float e = expf(S[tid*16+jj] - mx);
                        Pp[tid*16+jj] = e; den += e;
                    }
                    s_iSg[tid] = 1.f / den;
                }
                __syncthreads();
                if (tid < 256) {
                    int mm = tid >> 6, d = tid & 63;
                    float o = 0.f;
                    for (int jj = 0; jj < nk; jj++)
                        o += Pp[mm*16+jj]*g_svc[((size_t)(l*BB+mm)*TT+jj)*DDIM + h*DH + d];
                    AO[mm*64+d] = o * s_iSg[mm];
                }
                __syncthreads();
                {
                    float a0=0.f, a1=0.f, a2=0.f, a3=0.f;
                    const float* wso = so + l*DD2 + (size_t)(h*DH)*DDIM + tid;
                    for (int d0 = 0; d0 < 64; d0 += 32) {
                        float wv[32];
                        #pragma unroll
                        for (int d = 0; d < 32; d++) wv[d] = wso[(size_t)(d0+d)*DDIM];
                        #pragma unroll
                        for (int d = 0; d < 32; d++) {
                            a0 += AO[      d0+d]*wv[d]; a1 += AO[ 64+d0+d]*wv[d];
                            a2 += AO[128+d0+d]*wv[d];   a3 += AO[192+d0+d]*wv[d];
                        }
                    }
                    g_p3[(h*4+0)*DDIM + tid] = a0;
                    g_p3[(h*4+1)*DDIM + tid] = a1;
                    g_p3[(h*4+2)*DDIM + tid] = a2;
                    g_p3[(h*4+3)*DDIM + tid] = a3;
                }
            } else if (l == 1 && bid < 12) {
                materialize_x(g_p8, bid - 8);   // fold layer-0 FFN into g_xd
            }
            gridbar(gen);

            // ---- S3: per-head [rms(ln2, x+P3) + cross-Q + cross-attn + O-proj partial] ----
            if (bid < 8) {
                int h = bid;
                float* xs = s_xs;           // [m*512+k]  (ln2-scaled)
                float* QQ = s_xs + 2048;    // [m*64+c]
                float* SC = s_xs + 2304;    // [m*64+j]
                float* PV = s_xs + 2560;    // [m*64+j]
                float* AO = s_xs + 2816;    // [m*64+d]
                float* QP = s_xs + 4096;    // [(ks*4+m)*64+c]
                {
                    float v0 = g_xd[tid], v1 = g_xd[512+tid], v2 = g_xd[1024+tid], v3 = g_xd[1536+tid];
                    #pragma unroll
                    for (int hh = 0; hh < 8; hh++) {
                        v0 += g_p3[(hh*4+0)*512+tid]; v1 += g_p3[(hh*4+1)*512+tid];
                        v2 += g_p3[(hh*4+2)*512+tid]; v3 += g_p3[(hh*4+3)*512+tid];
                    }
                    if (h == 0) {  // publish summed residual for S4
                        g_x2[tid] = v0; g_x2[512+tid] = v1;
                        g_x2[1024+tid] = v2; g_x2[1536+tid] = v3;
                    }
                    float lw = ln2[l*DDIM + tid];
                    rms_stats(v0, v1, v2, v3);
                    xs[tid] = v0*lw; xs[512+tid] = v1*lw; xs[1024+tid] = v2*lw; xs[1536+tid] = v3*lw;
                }
                __syncthreads();
                // cross-Q slice: q[m][c] = sinv[m] * sum_k xs[m][k]*cq[k][h*64+c]
                {
                    int c = tid & 63, ks = tid >> 6;
                    const float* wq = cq + l*DD2 + (size_t)(ks*64)*DDIM + h*DH + c;
                    float q0=0.f, q1=0.f, q2=0.f, q3=0.f;
                    for (int k0 = 0; k0 < 64; k0 += 32) {
                        float wv[32];
                        #pragma unroll
                        for (int k = 0; k < 32; k++) wv[k] = wq[(size_t)(k0+k)*DDIM];
                        #pragma unroll
                        for (int k = 0; k < 32; k++) {
                            int kk = ks*64 + k0 + k;
                            q0 += xs[kk]*wv[k];      q1 += xs[512+kk]*wv[k];
                            q2 += xs[1024+kk]*wv[k]; q3 += xs[1536+kk]*wv[k];
                        }
                    }
                    QP[(ks*4+0)*64+c] = q0; QP[(ks*4+1)*64+c] = q1;
                    QP[(ks*4+2)*64+c] = q2; QP[(ks*4+3)*64+c] = q3;
                }
                __syncthreads();
                if (tid < 256) {
                    int mm = tid >> 6, cc = tid & 63;
                    float q = 0.f;
                    #pragma unroll
                    for (int ks2 = 0; ks2 < 8; ks2++) q += QP[(ks2*4+mm)*64+cc];
                    QQ[mm*64+cc] = q * s_sinv[mm];
                }
                __syncthreads();
                // scores over 64 encoder keys
                {
                    int m = tid >> 7, j = (tid >> 1) & 63, d32 = tid & 1;
                    const float* kr = g_ckc + ((size_t)(l*BB+m)*SS + j)*DDIM + h*DH + d32*32;
                    const float* qq = QQ + m*64 + d32*32;
                    float sc = 0.f;
                    #pragma unroll
                    for (int dd = 0; dd < 32; dd++) sc += qq[dd]*kr[dd];
                    sc += __shfl_xor_sync(0xffffffffu, sc, 1);
                    if (d32 == 0)
                        SC[m*64+j] = sc * 0.125f + (1.f - mask[m*SS + j]) * NEGV;
                }
                __syncthreads();
                // softmax per m (warp m handles 64 scores)
                {
                    int w = tid >> 5, lane = tid & 31;
                    if (w < 4) {
                        float va = SC[w*64+lane], vb = SC[w*64+32+lane];
                        float mx = fmaxf(va, vb);
                        #pragma unroll
                        for (int off = 16; off > 0; off >>= 1)
                            mx = fmaxf(mx, __shfl_xor_sync(0xffffffffu, mx, off));
                        float ea = expf(va-mx), eb = expf(vb-mx);
                        float den = ea + eb;
                        #pragma unroll
                        for (int off = 16; off > 0; off >>= 1)
                            den += __shfl_xor_sync(0xffffffffu, den, off);
                        PV[w*64+lane] = ea; PV[w*64+32+lane] = eb;
                        if (lane == 0) s_iSg[w] = 1.f/den;
                    }
                }
                __syncthreads();
                if (tid < 256) {
                    int mm = tid >> 6, d = tid & 63;
                    float o = 0.f;
                    const float* vr = g_cvc + ((size_t)(l*BB+mm)*SS)*DDIM + h*DH + d;
                    #pragma unroll 16
                    for (int jj = 0; jj < 64; jj++)
                        o += PV[mm*64+jj]*vr[(size_t)jj*DDIM];
                    AO[mm*64+d] = o * s_iSg[mm];
                }
                __syncthreads();
                {
                    float a0=0.f, a1=0.f, a2=0.f, a3=0.f;
                    const float* wco = co + l*DD2 + (size_t)(h*DH)*DDIM + tid;
                    for (int d0 = 0; d0 < 64; d0 += 32) {
                        float wv[32];
                        #pragma unroll
                        for (int d = 0; d < 32; d++) wv[d] = wco[(size_t)(d0+d)*DDIM];
                        #pragma unroll
                        for (int d = 0; d < 32; d++) {
                            a0 += AO[      d0+d]*wv[d]; a1 += AO[ 64+d0+d]*wv[d];
                            a2 += AO[128+d0+d]*wv[d];   a3 += AO[192+d0+d]*wv[d];
                        }
                    }
                    g_p6[(h*4+0)*DDIM + tid] = a0;
                    g_p6[(h*4+1)*DDIM + tid] = a1;
                    g_p6[(h*4+2)*DDIM + tid] = a2;
                    g_p6[(h*4+3)*DDIM + tid] = a3;
                }
            }
            gridbar(gen);

            // ---- S4: rms(ln3, x2+P6) + W1 (128 blocks); bid 0 publishes x3 ----
            if (bid < 128) {
                {
                    float v0 = g_x2[tid], v1 = g_x2[512+tid], v2 = g_x2[1024+tid], v3 = g_x2[1536+tid];
                    #pragma unroll
                    for (int hh = 0; hh < 8; hh++) {
                        v0 += g_p6[(hh*4+0)*512+tid]; v1 += g_p6[(hh*4+1)*512+tid];
                        v2 += g_p6[(hh*4+2)*512+tid]; v3 += g_p6[(hh*4+3)*512+tid];
                    }
                    if (bid == 0) {
                        g_x3[tid] = v0; g_x3[512+tid] = v1;
                        g_x3[1024+tid] = v2; g_x3[1536+tid] = v3;
                    }
                    float lw = ln3[l*DDIM + tid];
                    rms_stats(v0, v1, v2, v3);
                    s_xs[tid] = v0*lw; s_xs[512+tid] = v1*lw;
                    s_xs[1024+tid] = v2*lw; s_xs[1536+tid] = v3*lw;
                }
                __syncthreads();
                gemv_tile<DDIM>(w1 + l*DF, DFF, bid, g_fd, DFF, true);
            }
            gridbar(gen);

            // ---- S5: relu + W2 partials (128 blocks); bid 128 installs x3 -> g_xd ----
            if (bid < 128) {
                prep_relu2048(g_fd);
                gemv_part<DFF, 4>(w2 + l*DF, DDIM, bid & 31, bid >> 5, g_p8, false);
            } else if (bid == 128) {
                #pragma unroll
                for (int m = 0; m < 4; m++) g_xd[m*512 + tid] = g_x3[m*512 + tid];
            }
            gridbar(gen);
        }

        // ---- logits + fused per-block softmax stats ----
        prep512p(g_xd, g_p8, lnf, true);
        logits_warp_stats(lm, g_logits);
        gridbar(gen);

        // ---- C (merged): redundant stat aggregate + probs + yemb + zero/pred ----
        {
            int w = tid >> 5, lane = tid & 31;
            if (w < 4) {
                float m = -1e30f, s = 0.f; int i = 0x7fffffff;
                for (int j = lane; j < NB; j += 32)
                    smerge(m, s, i, g_stm[w*NB + j], g_sts[w*NB + j], g_sti[w*NB + j]);
                #pragma unroll
                for (int off = 16; off > 0; off >>= 1) {
                    float m2 = __shfl_xor_sync(0xffffffffu, m, off);
                    float s2 = __shfl_xor_sync(0xffffffffu, s, off);
                    int   i2 = __shfl_xor_sync(0xffffffffu, i, off);
                    smerge(m, s, i, m2, s2, i2);
                }
                if (lane == 0) { s_Mg[w] = m; s_iSg[w] = 1.f/s; s_amg[w] = i; }
            }
            __syncthreads();
            if (bid == 0) {
                #pragma unroll
                for (int p = 0; p < 4; p++) g_xd[p*512 + tid] = 0.f;
                __syncthreads();
                if (tid == 0) { __threadfence(); *(volatile unsigned*)&g_zflag = gen; }
                if (tid < 4)
                    out[(size_t)BB*TT*VV + tid*TT + t] = (s_amg[tid] == 0) ? 1.0f : 0.0f;
            }
            float M0 = s_Mg[0], M1 = s_Mg[1], M2 = s_Mg[2], M3 = s_Mg[3];
            float iS0 = s_iSg[0], iS1 = s_iSg[1], iS2 = s_iSg[2], iS3 = s_iSg[3];
            float a0=0.f, a1=0.f, a2=0.f, a3=0.f;
            int d = tid;
            for (int t0 = bid; t0 < VV/128; t0 += NB) {
                int v0 = t0*128;
                __syncthreads();
                {
                    int m = tid >> 7, j = tid & 127;
                    float lg = g_logits[(size_t)m*VV + v0 + j];
                    float Mv  = (m == 0) ? M0  : (m == 1) ? M1  : (m == 2) ? M2  : M3;
                    float iSv = (m == 0) ? iS0 : (m == 1) ? iS1 : (m == 2) ? iS2 : iS3;
                    float p = expf(lg - Mv) * iSv;
                    out[(size_t)(m*TT + t)*VV + v0 + j] = p;
                    s_red[m*128 + j] = p;
                }
                __syncthreads();
                if (t + 1 < TT) {
                    for (int j0 = 0; j0 < 128; j0 += 32) {
                        float ev[32];
                        #pragma unroll
                        for (int j = 0; j < 32; j++)
                            ev[j] = emb[(size_t)(v0 + j0 + j)*DDIM + d];
                        #pragma unroll
                        for (int j = 0; j < 32; j++) {
                            a0 += s_red[j0+j]*ev[j];     a1 += s_red[128+j0+j]*ev[j];
                            a2 += s_red[256+j0+j]*ev[j]; a3 += s_red[384+j0+j]*ev[j];
                        }
                    }
                }
            }
            if (t + 1 < TT) {
                if (tid == 0) { while (*(volatile unsigned*)&g_zflag < gen) { } }
                __syncthreads();
                atomicAdd(&g_xd[0*DDIM + d], a0);
                atomicAdd(&g_xd[1*DDIM + d], a1);
                atomicAdd(&g_xd[2*DDIM + d], a2);
                atomicAdd(&g_xd[3*DDIM + d], a3);
            }
        }
        gridbar(gen);
    }
}

// ---------------- launcher ----------------
extern "C" void kernel_launch(void* const* d_in, const int* in_sizes, int n_in,
                              void* d_out, int out_size) {
    const int*   ids     = (const int*)  d_in[0];
    const float* mask    = (const float*)d_in[1];
    const float* emb     = (const float*)d_in[2];
    const float* enc_wq  = (const float*)d_in[3];
    const float* enc_wk  = (const float*)d_in[4];
    const float* enc_wv  = (const float*)d_in[5];
    const float* enc_wo  = (const float*)d_in[6];
    const float* enc_ln1 = (const float*)d_in[7];
    const float* enc_w1  = (const float*)d_in[8];
    const float* enc_w2  = (const float*)d_in[9];
    const float* enc_ln2 = (const float*)d_in[10];
    const float* enc_lnf = (const float*)d_in[11];
    const float* dec_sq  = (const float*)d_in[12];
    const float* dec_sk  = (const float*)d_in[13];
    const float* dec_sv  = (const float*)d_in[14];
    const float* dec_so  = (const float*)d_in[15];
    const float* dec_ln1 = (const float*)d_in[16];
    const float* dec_cq  = (const float*)d_in[17];
    const float* dec_ck  = (const float*)d_in[18];
    const float* dec_cv  = (const float*)d_in[19];
    const float* dec_co  = (const float*)d_in[20];
    const float* dec_ln2 = (const float*)d_in[21];
    const float* dec_w1  = (const float*)d_in[22];
    const float* dec_w2  = (const float*)d_in[23];
    const float* dec_ln3 = (const float*)d_in[24];
    const float* dec_lnf = (const float*)d_in[25];
    const float* lm      = (const float*)d_in[26];
    float* out = (float*)d_out;

    float *gx, *gh, *gq, *gk, *gv, *gat, *gff, *ghs, *gckc, *gcvc, *gpart;
    cudaGetSymbolAddress((void**)&gx,   g_x);
    cudaGetSymbolAddress((void**)&gh,   g_h);
    cudaGetSymbolAddress((void**)&gq,   g_q);
    cudaGetSymbolAddress((void**)&gk,   g_k);
    cudaGetSymbolAddress((void**)&gv,   g_v);
    cudaGetSymbolAddress((void**)&gat,  g_at);
    cudaGetSymbolAddress((void**)&gff,  g_ff);
    cudaGetSymbolAddress((void**)&ghs,  g_hs);
    cudaGetSymbolAddress((void**)&gckc, g_ckc);
    cudaGetSymbolAddress((void**)&gcvc, g_cvc);
    cudaGetSymbolAddress((void**)&gpart, g_part);

    const int MROWS = BB*SS;
    const size_t DD2 = (size_t)DDIM*DDIM;
    const size_t DF  = (size_t)DDIM*DFF;
    const int MN_DD = MROWS*DDIM;
    const int MN_DF = MROWS*DFF;

    #define GEMM_DD(A, W, RES, C, FLAGS) do {                                          \
        gemm_split<<<dim3(DDIM/64, MROWS/64, 8), 256>>>(A, W, gpart, MROWS, DDIM, DDIM, 8); \
        gemm_reduce<<<MN_DD/1024, 256>>>(gpart, RES, C, MN_DD, 8, FLAGS);              \
    } while (0)

    // ===== encoder =====
    embed_kernel<<<MROWS, 256>>>(ids, emb);
    for (int l = 0; l < LLAY; l++) {
        rmsnorm_kernel<<<MROWS, 256>>>(gx, enc_ln1 + l*DDIM, gh);
        gemm_split3<<<dim3(DDIM/64, MROWS/64, 24), 256>>>(
            gh, enc_wq + l*DD2, enc_wk + l*DD2, enc_wv + l*DD2,
            gpart, MROWS, DDIM, DDIM, 8);
        gemm_reduce3<<<dim3(MN_DD/1024, 3), 256>>>(gpart, gq, gk, gv, MN_DD, 8);
        enc_attn<<<BB*HH, 64>>>(gq, gk, gv, mask, gat);
        GEMM_DD(gat, enc_wo + l*DD2, gx, gx, GF_RES);
        rmsnorm_kernel<<<MROWS, 256>>>(gx, enc_ln2 + l*DDIM, gh);
        gemm_split<<<dim3(DFF/64, MROWS/64, 2), 256>>>(gh, enc_w1 + l*DF, gpart, MROWS, DFF, DDIM, 2);
        gemm_reduce<<<MN_DF/1024, 256>>>(gpart, nullptr, gff, MN_DF, 2, GF_RELU);
        gemm_split<<<dim3(DDIM/64, MROWS/64, 8), 256>>>(gff, enc_w2 + l*DF, gpart, MROWS, DDIM, DFF, 8);
        gemm_reduce<<<MN_DD/1024, 256>>>(gpart, gx, gx, MN_DD, 8, GF_RES);
    }
    rmsnorm_kernel<<<MROWS, 256>>>(gx, enc_lnf, ghs);

    // cross K/V precompute (batched)
    for (int l = 0; l < LLAY; l++) {
        gemm_split3<<<dim3(DDIM/64, MROWS/64, 16), 256>>>(
            ghs, dec_ck + l*DD2, dec_cv + l*DD2, dec_cv + l*DD2,
            gpart, MROWS, DDIM, DDIM, 8);
        gemm_reduce3<<<dim3(MN_DD/1024, 2), 256>>>(
            gpart, gckc + (size_t)l*MROWS*DDIM, gcvc + (size_t)l*MROWS*DDIM,
            gcvc + (size_t)l*MROWS*DDIM, MN_DD, 8);
    }

    // ===== full 16-iteration decode in ONE persistent kernel =====
    decode_megakernel<<<NB, NT>>>(mask, emb,
                                  dec_sq, dec_sk, dec_sv, dec_so, dec_ln1,
                                  dec_cq, dec_co, dec_ln2,
                                  dec_w1, dec_w2, dec_ln3, dec_lnf,
                                  lm, out);
}